// round 8
// baseline (speedup 1.0000x reference)
#include <cuda_runtime.h>
#include <math.h>

#define PI_F 3.14159265358979323846f
#define N_NODES 4096
#define N_EDGES 12288
#define NUM_GRAPHS 16
#define PQC_BLOCKS 1024

// ---------------- device scratch ----------------
__device__ float  g_x[N_NODES * 2];     // node angles (update-MLP input & segment sum)
__device__ float4 g_x4[N_NODES];        // node wire amplitudes
__device__ float4 g_e4[N_EDGES];        // edge wire amplitudes
// gate table: [0..15] FB1 (4 branch matrices for a1), [16..31] FB0 (a2),
// [32..35] Re, [36..39] Rnb, [40..43] Ra1p, [44..47] Rnbp, [48..51] Q3, [52..55] Q1
__device__ float2 g_gates[56];
__device__ float2 g_w[64];              // 4 precomputed iter0 output columns (16 each)
__device__ float  g_gsum[NUM_GRAPHS * 2];
__device__ float  g_gcnt[NUM_GRAPHS];
__device__ int    g_done;

// ---------------- complex helpers ----------------
__device__ __forceinline__ float2 cmul(float2 a, float2 b) {
    return make_float2(fmaf(a.x, b.x, -(a.y * b.y)), fmaf(a.x, b.y, a.y * b.x));
}
__device__ __forceinline__ float2 cfma(float2 a, float2 b, float2 c) {   // a*b + c
    return make_float2(fmaf(a.x, b.x, fmaf(-a.y, b.y, c.x)),
                       fmaf(a.x, b.y, fmaf( a.y, b.x, c.y)));
}
__device__ __forceinline__ float2 cadd(float2 a, float2 b) {
    return make_float2(a.x + b.x, a.y + b.y);
}

// ================= PQC register-gate primitives (scalar float2) =================
// Register bits: R0=a2, R1=a1, R2=nb, R3=e
template <int J>
__device__ __forceinline__ void ap_reg(float2* v, const float2* U) {
    float2 u0 = U[0], u1 = U[1], u2 = U[2], u3 = U[3];
#pragma unroll
    for (int r = 0; r < 16; r++) {
        if ((r >> J) & 1) continue;
        int r2 = r | (1 << J);
        float2 a = v[r], b = v[r2];
        v[r]  = cfma(u1, b, cmul(u0, a));
        v[r2] = cfma(u3, b, cmul(u2, a));
    }
}
// 1q gate on register bit J (J in {0,1}), matrix selected by bits (3,2).
// Branch-grouped: amplitudes for branch b are exactly r in [4b, 4b+4),
// so only ONE branch matrix is live at a time (liveness ~8 floats, not 32).
template <int J>
__device__ __forceinline__ void ap_branch(float2* v, const float2* FB) {
#pragma unroll
    for (int b = 0; b < 4; b++) {
        float2 u0 = FB[4 * b], u1 = FB[4 * b + 1], u2 = FB[4 * b + 2], u3 = FB[4 * b + 3];
#pragma unroll
        for (int r = 4 * b; r < 4 * b + 4; r++) {
            if ((r >> J) & 1) continue;
            int r2 = r | (1 << J);
            float2 a = v[r], bb = v[r2];
            v[r]  = cfma(u1, bb, cmul(u0, a));
            v[r2] = cfma(u3, bb, cmul(u2, a));
        }
    }
}
template <int C, int T>
__device__ __forceinline__ void cnot_rr(float2* v) {
#pragma unroll
    for (int r = 0; r < 16; r++) {
        if (!((r >> C) & 1) || ((r >> T) & 1)) continue;
        int r2 = r | (1 << T);
        float2 t = v[r]; v[r] = v[r2]; v[r2] = t;
    }
}
template <int J>
__device__ __forceinline__ void swap_reg_lane(float2* v, int lane, int mask) {
    bool b = lane & mask;
#pragma unroll
    for (int r = 0; r < 16; r++) {
        if ((r >> J) & 1) continue;
        int r2 = r | (1 << J);
        float2 send = b ? v[r] : v[r2];
        float2 recv;
        recv.x = __shfl_xor_sync(0xffffffffu, send.x, mask);
        recv.y = __shfl_xor_sync(0xffffffffu, send.y, mask);
        if (b) v[r] = recv; else v[r2] = recv;
    }
}

// one ctrl+sel+sel iteration (branch-fused controlled gates)
__device__ __forceinline__ void iter_regs(float2* v, const float2* sG) {
    ap_branch<1>(v, sG);          // FB1 = Ra1 * CRY(e->a1) * CRX(nb->a1)
    ap_branch<0>(v, sG + 16);     // FB0 = Ra2 * CRY(e->a2) * CRZ(nb->a2)
    ap_reg<3>(v, sG + 32);        // Re
    ap_reg<2>(v, sG + 36);        // Rnb
    cnot_rr<3, 2>(v);
    cnot_rr<2, 1>(v);
    cnot_rr<1, 3>(v);
    ap_reg<1>(v, sG + 40);        // Ra1'
    ap_reg<2>(v, sG + 44);        // Rnb'
    cnot_rr<1, 2>(v);
    cnot_rr<2, 0>(v);
    cnot_rr<0, 1>(v);
}

// ---------------- gate precompute ----------------
__device__ void make_rot(const float* w, float2* m) {
    float phi = w[0], th = w[1], om = w[2];
    float c, s; sincosf(th * 0.5f, &s, &c);
    float sa, ca, sb, cb;
    sincosf((phi + om) * 0.5f, &sa, &ca);
    sincosf((phi - om) * 0.5f, &sb, &cb);
    m[0] = make_float2(c * ca, -c * sa);
    m[1] = make_float2(-s * cb, -s * sb);
    m[2] = make_float2(s * cb, -s * sb);
    m[3] = make_float2(c * ca, c * sa);
}
__device__ void cm2(const float2* A, const float2* B, float2* C) {
    C[0] = cadd(cmul(A[0], B[0]), cmul(A[1], B[2]));
    C[1] = cadd(cmul(A[0], B[1]), cmul(A[1], B[3]));
    C[2] = cadd(cmul(A[2], B[0]), cmul(A[3], B[2]));
    C[3] = cadd(cmul(A[2], B[1]), cmul(A[3], B[3]));
}

__device__ void prep_gates(const float* strong, const float* inits, const float* update) {
    float c, s;
    float2 RX0[4], RY1[4], RZ2[4], RY3[4], I2[4];
    I2[0] = make_float2(1, 0); I2[1] = make_float2(0, 0);
    I2[2] = make_float2(0, 0); I2[3] = make_float2(1, 0);
    sincosf(inits[0] * 0.5f, &s, &c);
    RX0[0] = make_float2(c, 0); RX0[1] = make_float2(0, -s);
    RX0[2] = make_float2(0, -s); RX0[3] = make_float2(c, 0);
    sincosf(inits[1] * 0.5f, &s, &c);
    RY1[0] = make_float2(c, 0); RY1[1] = make_float2(-s, 0);
    RY1[2] = make_float2(s, 0); RY1[3] = make_float2(c, 0);
    sincosf(inits[2] * 0.5f, &s, &c);
    RZ2[0] = make_float2(c, -s); RZ2[1] = make_float2(0, 0);
    RZ2[2] = make_float2(0, 0);  RZ2[3] = make_float2(c, s);
    sincosf(inits[3] * 0.5f, &s, &c);
    RY3[0] = make_float2(c, 0); RY3[1] = make_float2(-s, 0);
    RY3[2] = make_float2(s, 0); RY3[3] = make_float2(c, 0);

    float2 Re[4], Rnb[4], Ra1[4], Ra1p[4], Rnbp[4], Ra2[4], U0[4], U1[4];
    make_rot(strong + 0,  Re);
    make_rot(strong + 3,  Rnb);
    make_rot(strong + 6,  Ra1);
    make_rot(strong + 9,  Ra1p);
    make_rot(strong + 12, Rnbp);
    make_rot(strong + 15, Ra2);
    make_rot(update + 0,  U0);
    make_rot(update + 3,  U1);

    float2 T[4], M[4];
    // FB1[b3*2+b2] = Ra1 * RY1^{b3} * RX0^{b2}   (b3 = e bit, b2 = nb bit)
    for (int b3 = 0; b3 < 2; b3++)
        for (int b2 = 0; b2 < 2; b2++) {
            cm2(b3 ? RY1 : I2, b2 ? RX0 : I2, T);
            cm2(Ra1, T, M);
            for (int k = 0; k < 4; k++) g_gates[(b3 * 2 + b2) * 4 + k] = M[k];
        }
    // FB0[b3*2+b2] = Ra2 * RY3^{b3} * RZ2^{b2}
    for (int b3 = 0; b3 < 2; b3++)
        for (int b2 = 0; b2 < 2; b2++) {
            cm2(b3 ? RY3 : I2, b2 ? RZ2 : I2, T);
            cm2(Ra2, T, M);
            for (int k = 0; k < 4; k++) g_gates[16 + (b3 * 2 + b2) * 4 + k] = M[k];
        }
    for (int k = 0; k < 4; k++) g_gates[32 + k] = Re[k];
    for (int k = 0; k < 4; k++) g_gates[36 + k] = Rnb[k];
    for (int k = 0; k < 4; k++) g_gates[40 + k] = Ra1p[k];
    for (int k = 0; k < 4; k++) g_gates[44 + k] = Rnbp[k];
    // Q = H * U (observable diagonalization)
    const float rh = 0.70710678118654752f;
    float2 H2[4];
    H2[0] = make_float2(rh, 0); H2[1] = make_float2(rh, 0);
    H2[2] = make_float2(rh, 0); H2[3] = make_float2(-rh, 0);
    cm2(H2, U0, M); for (int k = 0; k < 4; k++) g_gates[48 + k] = M[k];
    cm2(H2, U1, M); for (int k = 0; k < 4; k++) g_gates[52 + k] = M[k];
}

// ---------------- fused node+edge MLP (+ prep + W columns) ----------------
template <int NI, bool IS_NODE>
__device__ __forceinline__ void mlp_row(const float* __restrict__ inp, int r,
                                        const float* sW1, const float* sb1,
                                        const float* sW2, const float* sb2) {
    float in[NI];
#pragma unroll
    for (int i = 0; i < NI; i++) in[i] = inp[r * NI + i];
    float o0 = sb2[0], o1 = sb2[1];
#pragma unroll 4
    for (int h = 0; h < 128; h++) {
        float a = sb1[h];
#pragma unroll
        for (int i = 0; i < NI; i++) a = fmaf(in[i], sW1[i * 128 + h], a);
        a = a > 0.f ? a : 0.01f * a;
        o0 = fmaf(a, sW2[2 * h], o0);
        o1 = fmaf(a, sW2[2 * h + 1], o1);
    }
    float t0 = tanhf(o0) * PI_F;   // ry
    float t1 = tanhf(o1) * PI_F;   // rz
    float sy, cy, sz, cz;
    sincosf(0.5f * t0, &sy, &cy);
    sincosf(0.5f * t1, &sz, &cz);
    float4 amps = make_float4(cy * cz, -cy * sz, sy * cz, sy * sz);
    if (IS_NODE) {
        g_x[2 * r] = t0; g_x[2 * r + 1] = t1;
        g_x4[r] = amps;
    } else {
        g_e4[r] = amps;
    }
}

__global__ void __launch_bounds__(128) mlp_fused_kernel(
    const float* __restrict__ node_feat,
    const float* __restrict__ Wn1, const float* __restrict__ bn1,
    const float* __restrict__ Wn2, const float* __restrict__ bn2,
    const float* __restrict__ edge_attr,
    const float* __restrict__ We1, const float* __restrict__ be1,
    const float* __restrict__ We2, const float* __restrict__ be2,
    const float* __restrict__ strong, const float* __restrict__ inits,
    const float* __restrict__ update) {
    __shared__ float sW1[8 * 128];
    __shared__ float sb1[128];
    __shared__ float sW2[256];
    __shared__ float sb2[2];
    int b = blockIdx.x, tid = threadIdx.x;
    bool isNode = (b < 32);
    const float* W1 = isNode ? Wn1 : We1;
    const float* b1 = isNode ? bn1 : be1;
    const float* W2 = isNode ? Wn2 : We2;
    const float* b2 = isNode ? bn2 : be2;
    int ni = isNode ? 8 : 4;
    for (int k = tid; k < ni * 128; k += 128) sW1[k] = W1[k];
    sb1[tid] = b1[tid];
    sW2[tid] = W2[tid]; sW2[128 + tid] = W2[128 + tid];
    if (tid < 2) sb2[tid] = b2[tid];

    if (b == 0) {
        if (tid < NUM_GRAPHS) {
            g_gsum[2 * tid] = 0.f; g_gsum[2 * tid + 1] = 0.f; g_gcnt[tid] = 0.f;
        }
        if (tid == 33) g_done = 0;
        if (tid == 32) prep_gates(strong, inits, update);
    }
    __syncthreads();

    // W columns: iter0 applied to basis states e_{8a+4b}, k = 2a+b
    if (b == 0 && tid >= 64 && tid < 68) {
        int k = tid - 64;
        float2 v[16];
#pragma unroll
        for (int r = 0; r < 16; r++) v[r] = make_float2(0.f, 0.f);
        v[((k >> 1) << 3) | ((k & 1) << 2)] = make_float2(1.f, 0.f);
        iter_regs(v, g_gates);
#pragma unroll
        for (int r = 0; r < 16; r++) g_w[k * 16 + r] = v[r];
    }

    if (isNode)
        mlp_row<8, true>(node_feat, b * 128 + tid, sW1, sb1, sW2, sb2);
    else
        mlp_row<4, false>(edge_attr, (b - 32) * 128 + tid, sW1, sb1, sW2, sb2);
}

// ================= PQC kernel: 128 threads (4 warps = 4 states) per block =================
__device__ __forceinline__ float2 pick(float4 a, int bit) {
    return bit ? make_float2(a.z, a.w) : make_float2(a.x, a.y);
}

__global__ void __launch_bounds__(128) pqc_kernel(
    const int* __restrict__ subgraphs, const int* __restrict__ edge_ids,
    const int* __restrict__ batch,
    const float* __restrict__ Wu1, const float* __restrict__ bu1,
    const float* __restrict__ Wu2, const float* __restrict__ bu2,
    const float* __restrict__ Wh1, const float* __restrict__ bh1,
    const float* __restrict__ Wh2, const float* __restrict__ bh2,
    float* __restrict__ out) {
    __shared__ float2 sG[56];
    __shared__ float2 sWC[64];
    __shared__ float sW1[384];
    __shared__ float sb1[128];
    __shared__ float sW2[256];
    __shared__ float sb2[2];
    __shared__ float sAcc[NUM_GRAPHS * 3];
    __shared__ int sLast;
    int tid = threadIdx.x;
    if (tid < 56) sG[tid] = g_gates[tid];
    if (tid >= 64 && tid < 128) sWC[tid - 64] = g_w[tid - 64];
    for (int k = tid; k < 384; k += 128) sW1[k] = Wu1[k];
    sb1[tid] = bu1[tid];
    sW2[tid] = Wu2[tid]; sW2[128 + tid] = Wu2[128 + tid];
    if (tid < 2) sb2[tid] = bu2[tid];
    if (tid < NUM_GRAPHS * 3) sAcc[tid] = 0.f;
    __syncthreads();

    int lane = tid & 31;
    int s = blockIdx.x * 4 + (tid >> 5);

    // lane bits: L4(16)=w1, L3(8)=w2, L2(4)=w3(n0), L1(2)=w5(n2), L0(1)=w6(n3)
    // reg bits:  R3=w0(e0), R2=w4(n1), R1=a1, R0=a2
    int e0 = edge_ids[3 * s], e1 = edge_ids[3 * s + 1], e2 = edge_ids[3 * s + 2];
    int n0 = subgraphs[4 * s], n1 = subgraphs[4 * s + 1],
        n2 = subgraphs[4 * s + 2], n3 = subgraphs[4 * s + 3];

    float x0c = g_x[2 * n0], x1c = g_x[2 * n0 + 1];

    float2 lf = pick(g_e4[e1], (lane >> 4) & 1);
    lf = cmul(lf, pick(g_e4[e2], (lane >> 3) & 1));
    lf = cmul(lf, pick(g_x4[n0], (lane >> 2) & 1));
    lf = cmul(lf, pick(g_x4[n2], (lane >> 1) & 1));
    lf = cmul(lf, pick(g_x4[n3], lane & 1));
    float4 aw0 = g_e4[e0];
    float4 aw4 = g_x4[n1];

    float2 c0 = cmul(lf, cmul(pick(aw0, 0), pick(aw4, 0)));
    float2 c1 = cmul(lf, cmul(pick(aw0, 0), pick(aw4, 1)));
    float2 c2 = cmul(lf, cmul(pick(aw0, 1), pick(aw4, 0)));
    float2 c3 = cmul(lf, cmul(pick(aw0, 1), pick(aw4, 1)));

    // post-iter0 state via precomputed columns
    float2 v[16];
#pragma unroll
    for (int r = 0; r < 16; r++)
        v[r] = cfma(c3, sWC[48 + r],
               cfma(c2, sWC[32 + r],
               cfma(c1, sWC[16 + r],
               cmul(c0, sWC[r]))));

    // retarget: R3: w0<->w1(L4), R2: w4<->w5(L1)
    swap_reg_lane<3>(v, lane, 16);
    swap_reg_lane<2>(v, lane, 2);
    iter_regs(v, sG);                     // iteration 1: e=w1, nb=w5
    swap_reg_lane<3>(v, lane, 8);
    swap_reg_lane<2>(v, lane, 1);
    iter_regs(v, sG);                     // iteration 2: e=w2, nb=w6
    swap_reg_lane<3>(v, lane, 4);         // R3 <- w3

    // final: Q3 on R3, Q1 on R1 (observable = Z3*Z1 after conjugation)
    ap_reg<3>(v, sG + 48);
    ap_reg<1>(v, sG + 52);

    // aggr = sum_r s_r |v_r|^2, s_r = +1 if bit3==bit1 else -1
    float part = 0.f;
#pragma unroll
    for (int r = 0; r < 16; r++) {
        float t = fmaf(v[r].x, v[r].x, v[r].y * v[r].y);
        part = (((r >> 3) ^ (r >> 1)) & 1) ? part - t : part + t;
    }
#pragma unroll
    for (int o = 16; o; o >>= 1) part += __shfl_xor_sync(0xffffffffu, part, o);
    float aggr = part;

    // fused update MLP: in = [x0c, x1c, aggr], 4 hidden units per lane
    float o0 = 0.f, o1 = 0.f;
#pragma unroll
    for (int k = 0; k < 4; k++) {
        int h = lane + 32 * k;
        float a = fmaf(x0c, sW1[h],
                  fmaf(x1c, sW1[128 + h],
                  fmaf(aggr, sW1[256 + h], sb1[h])));
        a = a > 0.f ? a : 0.01f * a;
        o0 = fmaf(a, sW2[2 * h], o0);
        o1 = fmaf(a, sW2[2 * h + 1], o1);
    }
#pragma unroll
    for (int o = 16; o; o >>= 1) {
        o0 += __shfl_xor_sync(0xffffffffu, o0, o);
        o1 += __shfl_xor_sync(0xffffffffu, o1, o);
    }
    if (lane == 0) {
        o0 += sb2[0]; o1 += sb2[1];
        int gu = batch[n0];
        int gx = batch[s];
        atomicAdd(&sAcc[3 * gu + 0], o0);
        atomicAdd(&sAcc[3 * gu + 1], o1);
        atomicAdd(&sAcc[3 * gx + 0], g_x[2 * s]);
        atomicAdd(&sAcc[3 * gx + 1], g_x[2 * s + 1]);
        atomicAdd(&sAcc[3 * gx + 2], 1.f);
    }
    __syncthreads();

    if (tid < NUM_GRAPHS) {
        atomicAdd(&g_gsum[2 * tid],     sAcc[3 * tid + 0]);
        atomicAdd(&g_gsum[2 * tid + 1], sAcc[3 * tid + 1]);
        atomicAdd(&g_gcnt[tid],         sAcc[3 * tid + 2]);
        __threadfence();
    }
    __syncthreads();
    if (tid == 0) {
        int old = atomicAdd(&g_done, 1);
        sLast = (old == PQC_BLOCKS - 1);
        __threadfence();
    }
    __syncthreads();

    if (sLast && tid < NUM_GRAPHS) {
        int g = tid;
        float cnt = __ldcg(&g_gcnt[g]);
        float g0 = __ldcg(&g_gsum[2 * g]) / cnt;
        float g1 = __ldcg(&g_gsum[2 * g + 1]) / cnt;
        float h0 = g0 * Wh1[0] + g1 * Wh1[2] + bh1[0];
        float h1 = g0 * Wh1[1] + g1 * Wh1[3] + bh1[1];
        h0 = h0 > 0.f ? h0 : 0.01f * h0;
        h1 = h1 > 0.f ? h1 : 0.01f * h1;
        out[2 * g]     = h0 * Wh2[0] + h1 * Wh2[2] + bh2[0];
        out[2 * g + 1] = h0 * Wh2[1] + h1 * Wh2[3] + bh2[1];
    }
}

// ---------------- launch ----------------
extern "C" void kernel_launch(void* const* d_in, const int* in_sizes, int n_in,
                              void* d_out, int out_size) {
    const float* node_feat = (const float*)d_in[0];
    const float* edge_attr = (const float*)d_in[1];
    const float* Wn1 = (const float*)d_in[2];
    const float* bn1 = (const float*)d_in[3];
    const float* Wn2 = (const float*)d_in[4];
    const float* bn2 = (const float*)d_in[5];
    const float* We1 = (const float*)d_in[6];
    const float* be1 = (const float*)d_in[7];
    const float* We2 = (const float*)d_in[8];
    const float* be2 = (const float*)d_in[9];
    const float* strong = (const float*)d_in[10];
    const float* inits  = (const float*)d_in[11];
    const float* update = (const float*)d_in[12];
    const float* Wu1 = (const float*)d_in[13];
    const float* bu1 = (const float*)d_in[14];
    const float* Wu2 = (const float*)d_in[15];
    const float* bu2 = (const float*)d_in[16];
    const float* Wh1 = (const float*)d_in[17];
    const float* bh1 = (const float*)d_in[18];
    const float* Wh2 = (const float*)d_in[19];
    const float* bh2 = (const float*)d_in[20];
    const int* subgraphs = (const int*)d_in[21];
    const int* edge_ids  = (const int*)d_in[22];
    const int* batch     = (const int*)d_in[23];
    float* out = (float*)d_out;

    mlp_fused_kernel<<<128, 128>>>(node_feat, Wn1, bn1, Wn2, bn2,
                                   edge_attr, We1, be1, We2, be2,
                                   strong, inits, update);
    pqc_kernel<<<PQC_BLOCKS, 128>>>(subgraphs, edge_ids, batch,
                                    Wu1, bu1, Wu2, bu2,
                                    Wh1, bh1, Wh2, bh2, out);
}

// round 9
// speedup vs baseline: 1.1078x; 1.1078x over previous
#include <cuda_runtime.h>
#include <math.h>

#define PI_F 3.14159265358979323846f
#define N_NODES 4096
#define N_EDGES 12288
#define NUM_GRAPHS 16
#define PQC_BLOCKS 1024

// ---------------- device scratch ----------------
__device__ float  g_x[N_NODES * 2];     // node angles (update-MLP input & segment sum)
__device__ float4 g_x4[N_NODES];        // node wire amplitudes
__device__ float4 g_e4[N_EDGES];        // edge wire amplitudes
// gate table (float2):
// [0..3]  (c,s) of CRX, CRY1, CRZ, CRY2 targets
// [4..7] Re  [8..11] Rnb  [12..15] Ra1  [16..19] Ra1p  [20..23] Rnbp  [24..27] Ra2
// [28..31] Q3 = H*U0   [32..35] Q1 = H*U1
__device__ float2 g_gates[36];
__device__ float2 g_w[64];              // 4 precomputed iter0 output columns (16 each)
__device__ float  g_gsum[NUM_GRAPHS * 2];
__device__ float  g_gcnt[NUM_GRAPHS];
__device__ int    g_done;

// ---------------- complex helpers ----------------
__device__ __forceinline__ float2 cmul(float2 a, float2 b) {
    return make_float2(fmaf(a.x, b.x, -(a.y * b.y)), fmaf(a.x, b.y, a.y * b.x));
}
__device__ __forceinline__ float2 cfma(float2 a, float2 b, float2 c) {   // a*b + c
    return make_float2(fmaf(a.x, b.x, fmaf(-a.y, b.y, c.x)),
                       fmaf(a.x, b.y, fmaf( a.y, b.x, c.y)));
}
__device__ __forceinline__ float2 cadd(float2 a, float2 b) {
    return make_float2(a.x + b.x, a.y + b.y);
}

// ================= PQC register-gate primitives (scalar float2) =================
// Register bits: R0=a2, R1=a1, R2=nb, R3=e
template <int J>
__device__ __forceinline__ void ap_reg(float2* v, const float2* U) {
    float2 u0 = U[0], u1 = U[1], u2 = U[2], u3 = U[3];
#pragma unroll
    for (int r = 0; r < 16; r++) {
        if ((r >> J) & 1) continue;
        int r2 = r | (1 << J);
        float2 a = v[r], b = v[r2];
        v[r]  = cfma(u1, b, cmul(u0, a));
        v[r2] = cfma(u3, b, cmul(u2, a));
    }
}
// controlled RX: active where control=1; target [[c,-is],[-is,c]]
template <int C, int T>
__device__ __forceinline__ void crx_rr(float2* v, float c, float s) {
#pragma unroll
    for (int r = 0; r < 16; r++) {
        if (!((r >> C) & 1) || ((r >> T) & 1)) continue;
        int r2 = r | (1 << T);
        float2 a = v[r], b = v[r2];
        v[r]  = make_float2(fmaf(c, a.x,  s * b.y), fmaf(c, a.y, -s * b.x));
        v[r2] = make_float2(fmaf(c, b.x,  s * a.y), fmaf(c, b.y, -s * a.x));
    }
}
// controlled RY: target [[c,-s],[s,c]] (real)
template <int C, int T>
__device__ __forceinline__ void cry_rr(float2* v, float c, float s) {
#pragma unroll
    for (int r = 0; r < 16; r++) {
        if (!((r >> C) & 1) || ((r >> T) & 1)) continue;
        int r2 = r | (1 << T);
        float2 a = v[r], b = v[r2];
        v[r]  = make_float2(fmaf(c, a.x, -s * b.x), fmaf(c, a.y, -s * b.y));
        v[r2] = make_float2(fmaf(c, b.x,  s * a.x), fmaf(c, b.y,  s * a.y));
    }
}
// controlled RZ: target diag(e^{-is}, e^{+is})
template <int C, int T>
__device__ __forceinline__ void crz_rr(float2* v, float c, float s) {
#pragma unroll
    for (int r = 0; r < 16; r++) {
        if (!((r >> C) & 1)) continue;
        float sg = ((r >> T) & 1) ? -s : s;
        float2 a = v[r];
        v[r] = make_float2(fmaf(c, a.x, sg * a.y), fmaf(c, a.y, -sg * a.x));
    }
}
template <int C, int T>
__device__ __forceinline__ void cnot_rr(float2* v) {
#pragma unroll
    for (int r = 0; r < 16; r++) {
        if (!((r >> C) & 1) || ((r >> T) & 1)) continue;
        int r2 = r | (1 << T);
        float2 t = v[r]; v[r] = v[r2]; v[r2] = t;
    }
}
template <int J>
__device__ __forceinline__ void swap_reg_lane(float2* v, int lane, int mask) {
    bool b = lane & mask;
#pragma unroll
    for (int r = 0; r < 16; r++) {
        if ((r >> J) & 1) continue;
        int r2 = r | (1 << J);
        float2 send = b ? v[r] : v[r2];
        float2 recv;
        recv.x = __shfl_xor_sync(0xffffffffu, send.x, mask);
        recv.y = __shfl_xor_sync(0xffffffffu, send.y, mask);
        if (b) v[r] = recv; else v[r2] = recv;
    }
}

// one ctrl+sel+sel iteration (R5 structure: low-liveness controlled gates)
__device__ __forceinline__ void iter_regs(float2* v, const float2* sG) {
    crx_rr<2, 1>(v, sG[0].x, sG[0].y);   // CRX(nb -> a1)
    cry_rr<3, 1>(v, sG[1].x, sG[1].y);   // CRY(e  -> a1)
    crz_rr<2, 0>(v, sG[2].x, sG[2].y);   // CRZ(nb -> a2)
    cry_rr<3, 0>(v, sG[3].x, sG[3].y);   // CRY(e  -> a2)
    ap_reg<3>(v, sG + 4);                // Re
    ap_reg<2>(v, sG + 8);                // Rnb
    ap_reg<1>(v, sG + 12);               // Ra1
    cnot_rr<3, 2>(v);
    cnot_rr<2, 1>(v);
    cnot_rr<1, 3>(v);
    ap_reg<1>(v, sG + 16);               // Ra1'
    ap_reg<2>(v, sG + 20);               // Rnb'
    ap_reg<0>(v, sG + 24);               // Ra2
    cnot_rr<1, 2>(v);
    cnot_rr<2, 0>(v);
    cnot_rr<0, 1>(v);
}

// ---------------- gate precompute ----------------
__device__ void make_rot(const float* w, float2* m) {
    float phi = w[0], th = w[1], om = w[2];
    float c, s; sincosf(th * 0.5f, &s, &c);
    float sa, ca, sb, cb;
    sincosf((phi + om) * 0.5f, &sa, &ca);
    sincosf((phi - om) * 0.5f, &sb, &cb);
    m[0] = make_float2(c * ca, -c * sa);
    m[1] = make_float2(-s * cb, -s * sb);
    m[2] = make_float2(s * cb, -s * sb);
    m[3] = make_float2(c * ca, c * sa);
}
__device__ void cm2(const float2* A, const float2* B, float2* C) {
    C[0] = cadd(cmul(A[0], B[0]), cmul(A[1], B[2]));
    C[1] = cadd(cmul(A[0], B[1]), cmul(A[1], B[3]));
    C[2] = cadd(cmul(A[2], B[0]), cmul(A[3], B[2]));
    C[3] = cadd(cmul(A[2], B[1]), cmul(A[3], B[3]));
}

__device__ void prep_gates(const float* strong, const float* inits, const float* update) {
    float c, s;
    sincosf(inits[0] * 0.5f, &s, &c); g_gates[0] = make_float2(c, s);  // CRX
    sincosf(inits[1] * 0.5f, &s, &c); g_gates[1] = make_float2(c, s);  // CRY1
    sincosf(inits[2] * 0.5f, &s, &c); g_gates[2] = make_float2(c, s);  // CRZ
    sincosf(inits[3] * 0.5f, &s, &c); g_gates[3] = make_float2(c, s);  // CRY2

    float2 M[4], Q[4];
    make_rot(strong + 0,  M); for (int k = 0; k < 4; k++) g_gates[4 + k]  = M[k];  // Re
    make_rot(strong + 3,  M); for (int k = 0; k < 4; k++) g_gates[8 + k]  = M[k];  // Rnb
    make_rot(strong + 6,  M); for (int k = 0; k < 4; k++) g_gates[12 + k] = M[k];  // Ra1
    make_rot(strong + 9,  M); for (int k = 0; k < 4; k++) g_gates[16 + k] = M[k];  // Ra1p
    make_rot(strong + 12, M); for (int k = 0; k < 4; k++) g_gates[20 + k] = M[k];  // Rnbp
    make_rot(strong + 15, M); for (int k = 0; k < 4; k++) g_gates[24 + k] = M[k];  // Ra2

    // observable diagonalization: Q = H * U  (final-sel U2 on a2 commutes out)
    const float rh = 0.70710678118654752f;
    float2 H2[4];
    H2[0] = make_float2(rh, 0); H2[1] = make_float2(rh, 0);
    H2[2] = make_float2(rh, 0); H2[3] = make_float2(-rh, 0);
    make_rot(update + 0, M); cm2(H2, M, Q); for (int k = 0; k < 4; k++) g_gates[28 + k] = Q[k];
    make_rot(update + 3, M); cm2(H2, M, Q); for (int k = 0; k < 4; k++) g_gates[32 + k] = Q[k];
}

// ---------------- fused node+edge MLP (+ prep + W columns) ----------------
template <int NI, bool IS_NODE>
__device__ __forceinline__ void mlp_row(const float* __restrict__ inp, int r,
                                        const float* sW1, const float* sb1,
                                        const float* sW2, const float* sb2) {
    float in[NI];
#pragma unroll
    for (int i = 0; i < NI; i++) in[i] = inp[r * NI + i];
    float o0 = sb2[0], o1 = sb2[1];
#pragma unroll 4
    for (int h = 0; h < 128; h++) {
        float a = sb1[h];
#pragma unroll
        for (int i = 0; i < NI; i++) a = fmaf(in[i], sW1[i * 128 + h], a);
        a = a > 0.f ? a : 0.01f * a;
        o0 = fmaf(a, sW2[2 * h], o0);
        o1 = fmaf(a, sW2[2 * h + 1], o1);
    }
    float t0 = tanhf(o0) * PI_F;   // ry
    float t1 = tanhf(o1) * PI_F;   // rz
    float sy, cy, sz, cz;
    sincosf(0.5f * t0, &sy, &cy);
    sincosf(0.5f * t1, &sz, &cz);
    float4 amps = make_float4(cy * cz, -cy * sz, sy * cz, sy * sz);
    if (IS_NODE) {
        g_x[2 * r] = t0; g_x[2 * r + 1] = t1;
        g_x4[r] = amps;
    } else {
        g_e4[r] = amps;
    }
}

__global__ void __launch_bounds__(128) mlp_fused_kernel(
    const float* __restrict__ node_feat,
    const float* __restrict__ Wn1, const float* __restrict__ bn1,
    const float* __restrict__ Wn2, const float* __restrict__ bn2,
    const float* __restrict__ edge_attr,
    const float* __restrict__ We1, const float* __restrict__ be1,
    const float* __restrict__ We2, const float* __restrict__ be2,
    const float* __restrict__ strong, const float* __restrict__ inits,
    const float* __restrict__ update) {
    __shared__ float sW1[8 * 128];
    __shared__ float sb1[128];
    __shared__ float sW2[256];
    __shared__ float sb2[2];
    int b = blockIdx.x, tid = threadIdx.x;
    bool isNode = (b < 32);
    const float* W1 = isNode ? Wn1 : We1;
    const float* b1 = isNode ? bn1 : be1;
    const float* W2 = isNode ? Wn2 : We2;
    const float* b2 = isNode ? bn2 : be2;
    int ni = isNode ? 8 : 4;
    for (int k = tid; k < ni * 128; k += 128) sW1[k] = W1[k];
    sb1[tid] = b1[tid];
    sW2[tid] = W2[tid]; sW2[128 + tid] = W2[128 + tid];
    if (tid < 2) sb2[tid] = b2[tid];

    if (b == 0) {
        if (tid < NUM_GRAPHS) {
            g_gsum[2 * tid] = 0.f; g_gsum[2 * tid + 1] = 0.f; g_gcnt[tid] = 0.f;
        }
        if (tid == 33) g_done = 0;
        if (tid == 32) prep_gates(strong, inits, update);
    }
    __syncthreads();

    // W columns: iter0 applied to basis states e_{8a+4b}, k = 2a+b
    if (b == 0 && tid >= 64 && tid < 68) {
        int k = tid - 64;
        float2 v[16];
#pragma unroll
        for (int r = 0; r < 16; r++) v[r] = make_float2(0.f, 0.f);
        v[((k >> 1) << 3) | ((k & 1) << 2)] = make_float2(1.f, 0.f);
        iter_regs(v, g_gates);
#pragma unroll
        for (int r = 0; r < 16; r++) g_w[k * 16 + r] = v[r];
    }

    if (isNode)
        mlp_row<8, true>(node_feat, b * 128 + tid, sW1, sb1, sW2, sb2);
    else
        mlp_row<4, false>(edge_attr, (b - 32) * 128 + tid, sW1, sb1, sW2, sb2);
}

// ================= PQC kernel: 128 threads (4 warps = 4 states) per block =================
__device__ __forceinline__ float2 pick(float4 a, int bit) {
    return bit ? make_float2(a.z, a.w) : make_float2(a.x, a.y);
}

__global__ void __launch_bounds__(128) pqc_kernel(
    const int* __restrict__ subgraphs, const int* __restrict__ edge_ids,
    const int* __restrict__ batch,
    const float* __restrict__ Wu1, const float* __restrict__ bu1,
    const float* __restrict__ Wu2, const float* __restrict__ bu2,
    const float* __restrict__ Wh1, const float* __restrict__ bh1,
    const float* __restrict__ Wh2, const float* __restrict__ bh2,
    float* __restrict__ out) {
    __shared__ float2 sG[36];
    __shared__ float2 sWC[64];
    __shared__ float sW1[384];
    __shared__ float sb1[128];
    __shared__ float sW2[256];
    __shared__ float sb2[2];
    __shared__ float sAcc[NUM_GRAPHS * 3];
    __shared__ int sLast;
    int tid = threadIdx.x;
    if (tid < 36) sG[tid] = g_gates[tid];
    if (tid >= 64) sWC[tid - 64] = g_w[tid - 64];
    for (int k = tid; k < 384; k += 128) sW1[k] = Wu1[k];
    sb1[tid] = bu1[tid];
    sW2[tid] = Wu2[tid]; sW2[128 + tid] = Wu2[128 + tid];
    if (tid < 2) sb2[tid] = bu2[tid];
    if (tid < NUM_GRAPHS * 3) sAcc[tid] = 0.f;
    __syncthreads();

    int lane = tid & 31;
    int s = blockIdx.x * 4 + (tid >> 5);

    // lane bits: L4(16)=w1, L3(8)=w2, L2(4)=w3(n0), L1(2)=w5(n2), L0(1)=w6(n3)
    // reg bits:  R3=w0(e0), R2=w4(n1), R1=a1, R0=a2
    int e0 = edge_ids[3 * s], e1 = edge_ids[3 * s + 1], e2 = edge_ids[3 * s + 2];
    int n0 = subgraphs[4 * s], n1 = subgraphs[4 * s + 1],
        n2 = subgraphs[4 * s + 2], n3 = subgraphs[4 * s + 3];

    float x0c = g_x[2 * n0], x1c = g_x[2 * n0 + 1];

    float2 lf = pick(g_e4[e1], (lane >> 4) & 1);
    lf = cmul(lf, pick(g_e4[e2], (lane >> 3) & 1));
    lf = cmul(lf, pick(g_x4[n0], (lane >> 2) & 1));
    lf = cmul(lf, pick(g_x4[n2], (lane >> 1) & 1));
    lf = cmul(lf, pick(g_x4[n3], lane & 1));
    float4 aw0 = g_e4[e0];
    float4 aw4 = g_x4[n1];

    float2 c0 = cmul(lf, cmul(pick(aw0, 0), pick(aw4, 0)));
    float2 c1 = cmul(lf, cmul(pick(aw0, 0), pick(aw4, 1)));
    float2 c2 = cmul(lf, cmul(pick(aw0, 1), pick(aw4, 0)));
    float2 c3 = cmul(lf, cmul(pick(aw0, 1), pick(aw4, 1)));

    // post-iter0 state via precomputed columns
    float2 v[16];
#pragma unroll
    for (int r = 0; r < 16; r++)
        v[r] = cfma(c3, sWC[48 + r],
               cfma(c2, sWC[32 + r],
               cfma(c1, sWC[16 + r],
               cmul(c0, sWC[r]))));

    // retarget: R3: w0<->w1(L4), R2: w4<->w5(L1)
    swap_reg_lane<3>(v, lane, 16);
    swap_reg_lane<2>(v, lane, 2);
    iter_regs(v, sG);                     // iteration 1: e=w1, nb=w5
    swap_reg_lane<3>(v, lane, 8);
    swap_reg_lane<2>(v, lane, 1);
    iter_regs(v, sG);                     // iteration 2: e=w2, nb=w6
    swap_reg_lane<3>(v, lane, 4);         // R3 <- w3

    // final: Q3 on R3, Q1 on R1 (observable = Z3*Z1 after conjugation; U2 drops)
    ap_reg<3>(v, sG + 28);
    ap_reg<1>(v, sG + 32);

    // aggr = sum_r s_r |v_r|^2, s_r = +1 if bit3==bit1 else -1
    float part = 0.f;
#pragma unroll
    for (int r = 0; r < 16; r++) {
        float t = fmaf(v[r].x, v[r].x, v[r].y * v[r].y);
        part = (((r >> 3) ^ (r >> 1)) & 1) ? part - t : part + t;
    }
#pragma unroll
    for (int o = 16; o; o >>= 1) part += __shfl_xor_sync(0xffffffffu, part, o);
    float aggr = part;

    // fused update MLP: in = [x0c, x1c, aggr], 4 hidden units per lane
    float o0 = 0.f, o1 = 0.f;
#pragma unroll
    for (int k = 0; k < 4; k++) {
        int h = lane + 32 * k;
        float a = fmaf(x0c, sW1[h],
                  fmaf(x1c, sW1[128 + h],
                  fmaf(aggr, sW1[256 + h], sb1[h])));
        a = a > 0.f ? a : 0.01f * a;
        o0 = fmaf(a, sW2[2 * h], o0);
        o1 = fmaf(a, sW2[2 * h + 1], o1);
    }
#pragma unroll
    for (int o = 16; o; o >>= 1) {
        o0 += __shfl_xor_sync(0xffffffffu, o0, o);
        o1 += __shfl_xor_sync(0xffffffffu, o1, o);
    }
    if (lane == 0) {
        o0 += sb2[0]; o1 += sb2[1];
        int gu = batch[n0];
        int gx = batch[s];
        atomicAdd(&sAcc[3 * gu + 0], o0);
        atomicAdd(&sAcc[3 * gu + 1], o1);
        atomicAdd(&sAcc[3 * gx + 0], g_x[2 * s]);
        atomicAdd(&sAcc[3 * gx + 1], g_x[2 * s + 1]);
        atomicAdd(&sAcc[3 * gx + 2], 1.f);
    }
    __syncthreads();

    if (tid < NUM_GRAPHS) {
        atomicAdd(&g_gsum[2 * tid],     sAcc[3 * tid + 0]);
        atomicAdd(&g_gsum[2 * tid + 1], sAcc[3 * tid + 1]);
        atomicAdd(&g_gcnt[tid],         sAcc[3 * tid + 2]);
        __threadfence();
    }
    __syncthreads();
    if (tid == 0) {
        int old = atomicAdd(&g_done, 1);
        sLast = (old == PQC_BLOCKS - 1);
        __threadfence();
    }
    __syncthreads();

    if (sLast && tid < NUM_GRAPHS) {
        int g = tid;
        float cnt = __ldcg(&g_gcnt[g]);
        float g0 = __ldcg(&g_gsum[2 * g]) / cnt;
        float g1 = __ldcg(&g_gsum[2 * g + 1]) / cnt;
        float h0 = g0 * Wh1[0] + g1 * Wh1[2] + bh1[0];
        float h1 = g0 * Wh1[1] + g1 * Wh1[3] + bh1[1];
        h0 = h0 > 0.f ? h0 : 0.01f * h0;
        h1 = h1 > 0.f ? h1 : 0.01f * h1;
        out[2 * g]     = h0 * Wh2[0] + h1 * Wh2[2] + bh2[0];
        out[2 * g + 1] = h0 * Wh2[1] + h1 * Wh2[3] + bh2[1];
    }
}

// ---------------- launch ----------------
extern "C" void kernel_launch(void* const* d_in, const int* in_sizes, int n_in,
                              void* d_out, int out_size) {
    const float* node_feat = (const float*)d_in[0];
    const float* edge_attr = (const float*)d_in[1];
    const float* Wn1 = (const float*)d_in[2];
    const float* bn1 = (const float*)d_in[3];
    const float* Wn2 = (const float*)d_in[4];
    const float* bn2 = (const float*)d_in[5];
    const float* We1 = (const float*)d_in[6];
    const float* be1 = (const float*)d_in[7];
    const float* We2 = (const float*)d_in[8];
    const float* be2 = (const float*)d_in[9];
    const float* strong = (const float*)d_in[10];
    const float* inits  = (const float*)d_in[11];
    const float* update = (const float*)d_in[12];
    const float* Wu1 = (const float*)d_in[13];
    const float* bu1 = (const float*)d_in[14];
    const float* Wu2 = (const float*)d_in[15];
    const float* bu2 = (const float*)d_in[16];
    const float* Wh1 = (const float*)d_in[17];
    const float* bh1 = (const float*)d_in[18];
    const float* Wh2 = (const float*)d_in[19];
    const float* bh2 = (const float*)d_in[20];
    const int* subgraphs = (const int*)d_in[21];
    const int* edge_ids  = (const int*)d_in[22];
    const int* batch     = (const int*)d_in[23];
    float* out = (float*)d_out;

    mlp_fused_kernel<<<128, 128>>>(node_feat, Wn1, bn1, Wn2, bn2,
                                   edge_attr, We1, be1, We2, be2,
                                   strong, inits, update);
    pqc_kernel<<<PQC_BLOCKS, 128>>>(subgraphs, edge_ids, batch,
                                    Wu1, bu1, Wu2, bu2,
                                    Wh1, bh1, Wh2, bh2, out);
}